// round 4
// baseline (speedup 1.0000x reference)
#include <cuda_runtime.h>
#include <cstdint>

#define B_ 2
#define H_ 8
#define S_ 1024
#define DK_ 64
#define DV_ 64
static constexpr float INV_T = 0.125f;                   // 1/temperature
static constexpr int OUT_ATTN_OFF = B_ * H_ * S_ * DV_;  // 1048576

// ---- packed fp32 helpers (sm_103a f32x2 pipe) -------------------------------
#define FMA2(acc, a, b) asm("fma.rn.f32x2 %0, %1, %2, %0;" : "+l"(acc) : "l"(a), "l"(b))

__device__ __forceinline__ unsigned long long dup2(float x) {
    unsigned long long r;
    asm("mov.b64 %0, {%1, %1};" : "=l"(r) : "f"(x));
    return r;
}
__device__ __forceinline__ float2 unpack2(unsigned long long v) {
    float2 r;
    asm("mov.b64 {%0, %1}, %2;" : "=f"(r.x), "=f"(r.y) : "l"(v));
    return r;
}

// ---------------------------------------------------------------------------
// K1: attn1[b,h,i,j] = (q/T)[b,h,i,:] . k[b,h,j,:]
// 128x128 CTA tile, 8x8 per-thread micro-tile, packed f32x2 accumulators
// (pairs of i-rows). Tiles staged transposed [d][row] with conflict-free STS.
// ---------------------------------------------------------------------------
static constexpr int K1_PITCH = 132;
static constexpr int K1_SMEM = 2 * 64 * K1_PITCH * 4;  // 67584 B

__global__ void __launch_bounds__(256) k1_qk(const float* __restrict__ q,
                                             const float* __restrict__ k,
                                             float* __restrict__ attn)
{
    extern __shared__ float sm1[];
    float* Qt = sm1;                   // [64][132]  Qt[d][i], pre-scaled by 1/T
    float* Kt = sm1 + 64 * K1_PITCH;   // [64][132]  Kt[d][j]

    const int bh = blockIdx.z;
    const int i0 = blockIdx.y * 128;
    const int j0 = blockIdx.x * 128;
    const float* qb = q + ((size_t)bh * S_ + i0) * DK_;
    const float* kb = k + ((size_t)bh * S_ + j0) * DK_;
    const int t = threadIdx.x;

    // stage + transpose; row = low bits => within-warp rows distinct mod 32
    // => STS.32 conflict-free. Global reads 16B/row at 256B stride (L2-hot).
    #pragma unroll
    for (int idx = t; idx < 2048; idx += 256) {
        const int row = idx & 127;
        const int d4  = ((idx >> 7) & 15) << 2;
        float4 a = *(const float4*)(qb + (size_t)row * DK_ + d4);
        Qt[(d4 + 0) * K1_PITCH + row] = a.x * INV_T;
        Qt[(d4 + 1) * K1_PITCH + row] = a.y * INV_T;
        Qt[(d4 + 2) * K1_PITCH + row] = a.z * INV_T;
        Qt[(d4 + 3) * K1_PITCH + row] = a.w * INV_T;
        float4 b = *(const float4*)(kb + (size_t)row * DK_ + d4);
        Kt[(d4 + 0) * K1_PITCH + row] = b.x;
        Kt[(d4 + 1) * K1_PITCH + row] = b.y;
        Kt[(d4 + 2) * K1_PITCH + row] = b.z;
        Kt[(d4 + 3) * K1_PITCH + row] = b.w;
    }
    __syncthreads();

    const int tx = t & 15, ty = t >> 4;
    const float* qp = Qt + ty * 8;
    const float* kp = Kt + tx * 8;

    unsigned long long acc[4][8] = {};  // acc[p][v]: i-pair (2p,2p+1) x j (v)

    #pragma unroll 4
    for (int d = 0; d < 64; d++) {
        const float* qd = qp + d * K1_PITCH;
        const float* kd = kp + d * K1_PITCH;
        ulonglong2 a01 = *(const ulonglong2*)qd;        // (i0,i1),(i2,i3)
        ulonglong2 a23 = *(const ulonglong2*)(qd + 4);  // (i4,i5),(i6,i7)
        float4 b0 = *(const float4*)kd;
        float4 b1 = *(const float4*)(kd + 4);
        unsigned long long av[4] = {a01.x, a01.y, a23.x, a23.y};
        unsigned long long bb[8] = {dup2(b0.x), dup2(b0.y), dup2(b0.z), dup2(b0.w),
                                    dup2(b1.x), dup2(b1.y), dup2(b1.z), dup2(b1.w)};
        #pragma unroll
        for (int p = 0; p < 4; p++)
            #pragma unroll
            for (int v = 0; v < 8; v++)
                FMA2(acc[p][v], av[p], bb[v]);
    }

    float* ab = attn + (((size_t)bh * S_ + i0 + ty * 8) * S_) + j0 + tx * 8;
    #pragma unroll
    for (int p = 0; p < 4; p++) {
        float r0[8], r1[8];
        #pragma unroll
        for (int v = 0; v < 8; v++) {
            float2 pv = unpack2(acc[p][v]);
            r0[v] = pv.x; r1[v] = pv.y;
        }
        float* row0 = ab + (size_t)(2 * p) * S_;
        float* row1 = ab + (size_t)(2 * p + 1) * S_;
        *(float4*)(row0)     = make_float4(r0[0], r0[1], r0[2], r0[3]);
        *(float4*)(row0 + 4) = make_float4(r0[4], r0[5], r0[6], r0[7]);
        *(float4*)(row1)     = make_float4(r1[0], r1[1], r1[2], r1[3]);
        *(float4*)(row1 + 4) = make_float4(r1[4], r1[5], r1[6], r1[7]);
    }
}

// ---------------------------------------------------------------------------
// K2: per (b,i): logits[h][j] = attn1[h][j] + qs[h,:] . rpr[b,i,j,:]
//     mask, softmax over j, write final probs. rpr streamed exactly once.
// Each thread owns one j per 256-chunk and all 8 heads (4 packed head-pair
// accumulators) -> each staged rpr value read once from smem.
// ---------------------------------------------------------------------------
static constexpr int K2_CHUNK = 256;
static constexpr int K2_RS_PITCH = 66;
static constexpr int K2_SMEM_QS = 512 * 4;                        // 2048 B
static constexpr int K2_SMEM_LOGIT = 8 * 1024 * 4;                // 32768 B
static constexpr int K2_SMEM_RS = K2_CHUNK * K2_RS_PITCH * 4;     // 67584 B
static constexpr int K2_SMEM_TOTAL = K2_SMEM_QS + K2_SMEM_LOGIT + K2_SMEM_RS;  // 102400

__global__ void __launch_bounds__(256) k2_rpr_softmax(
    const float* __restrict__ q,
    const float* __restrict__ rpr,
    const int* __restrict__ mask,
    float* __restrict__ attn)
{
    extern __shared__ char smem_raw[];
    float* qs    = (float*)smem_raw;                               // [4][64][2]
    float* logit = (float*)(smem_raw + K2_SMEM_QS);                // [8][1024]
    float* rs    = (float*)(smem_raw + K2_SMEM_QS + K2_SMEM_LOGIT);// [256][66]

    const int b = blockIdx.y;
    const int i = blockIdx.x;
    const int t = threadIdx.x;

    // qs[hp][d][c] = q[h=2hp+c][d] / T   (adjacent floats = head pair = f32x2)
    #pragma unroll
    for (int idx = t; idx < 512; idx += 256) {
        const int h = idx >> 6, d = idx & 63;
        qs[(((h >> 1) * 64) + d) * 2 + (h & 1)] =
            q[(((size_t)b * H_ + h) * S_ + i) * DK_ + d] * INV_T;
    }

    const float* rbase = rpr + ((size_t)b * S_ + i) * S_ * DK_;
    const int* mrow = mask + ((size_t)b * S_ + i) * S_;

    for (int jc = 0; jc < S_; jc += K2_CHUNK) {
        __syncthreads();  // qs ready (1st iter) / rs consumers done (later)
        // stage rpr chunk [256][64] -> rs (pitch 66, STS.64 at wavefront floor)
        const float4* src = (const float4*)(rbase + (size_t)jc * DK_);
        #pragma unroll
        for (int idx = t; idx < K2_CHUNK * 16; idx += 256) {
            const int jj = idx >> 4;
            const int d4 = (idx & 15) << 2;
            float4 v4 = src[idx];
            float* r = rs + jj * K2_RS_PITCH + d4;
            *(float2*)(r)     = make_float2(v4.x, v4.y);
            *(float2*)(r + 2) = make_float2(v4.z, v4.w);
        }
        __syncthreads();

        unsigned long long acc[4] = {};  // head pairs (h0,h1) packed
        const float* rr = rs + t * K2_RS_PITCH;
        #pragma unroll 8
        for (int d = 0; d < 64; d += 2) {
            float2 r2 = *(const float2*)(rr + d);
            unsigned long long rx = dup2(r2.x);
            unsigned long long ry = dup2(r2.y);
            #pragma unroll
            for (int hp = 0; hp < 4; hp++) {
                ulonglong2 qq = *(const ulonglong2*)(qs + hp * 128 + d * 2);
                FMA2(acc[hp], qq.x, rx);
                FMA2(acc[hp], qq.y, ry);
            }
        }

        const int j = jc + t;
        const int mk = mrow[j];
        #pragma unroll
        for (int hp = 0; hp < 4; hp++) {
            float2 av = unpack2(acc[hp]);
            const float a0 = attn[(((size_t)b * H_ + 2 * hp)     * S_ + i) * S_ + j];
            const float a1 = attn[(((size_t)b * H_ + 2 * hp + 1) * S_ + i) * S_ + j];
            logit[(2 * hp)     * 1024 + j] = mk ? (av.x + a0) : -1e9f;
            logit[(2 * hp + 1) * 1024 + j] = mk ? (av.y + a1) : -1e9f;
        }
    }
    __syncthreads();

    // softmax: warp w handles head w
    const int w = t >> 5, lane = t & 31;
    const float* lrow = logit + w * 1024;
    float vals[32];
    float mx = -3.4e38f;
    #pragma unroll
    for (int m = 0; m < 32; m++) {
        vals[m] = lrow[lane + 32 * m];
        mx = fmaxf(mx, vals[m]);
    }
    #pragma unroll
    for (int o = 16; o > 0; o >>= 1) mx = fmaxf(mx, __shfl_xor_sync(0xffffffffu, mx, o));
    float sum = 0.f;
    #pragma unroll
    for (int m = 0; m < 32; m++) { vals[m] = __expf(vals[m] - mx); sum += vals[m]; }
    #pragma unroll
    for (int o = 16; o > 0; o >>= 1) sum += __shfl_xor_sync(0xffffffffu, sum, o);
    const float rinv = 1.0f / sum;

    float* arow = attn + (((size_t)b * H_ + w) * S_ + i) * S_;
    #pragma unroll
    for (int m = 0; m < 32; m++) arow[lane + 32 * m] = vals[m] * rinv;
}

// ---------------------------------------------------------------------------
// K3: output[b,h,i,:] = sum_j attn[b,h,i,j] * v[b,h,j,:]
// Broadcast-A design: no transpose anywhere. Warp w owns 8 i-rows, lane owns
// an n-pair (f32x2). A values are warp-uniform smem broadcasts.
// ---------------------------------------------------------------------------
__global__ void __launch_bounds__(256) k3_av(const float* __restrict__ attn,
                                             const float* __restrict__ v,
                                             float* __restrict__ out)
{
    __shared__ float As[64][64];  // As[i][j]  (natural layout)
    __shared__ float Vs[64][64];  // Vs[j][n]  (natural layout)
    const int bh = blockIdx.y;
    const int i0 = blockIdx.x * 64;
    const int t = threadIdx.x;
    const int w = t >> 5, l = t & 31;
    const float* ab = attn + ((size_t)bh * S_ + i0) * S_;
    const float* vb = v + (size_t)bh * S_ * DV_;

    unsigned long long acc[8] = {};  // 8 i-rows x n-pair(2l,2l+1)

    for (int jc = 0; jc < S_; jc += 64) {
        __syncthreads();
        #pragma unroll
        for (int idx = t; idx < 1024; idx += 256) {
            const int row = idx >> 4;
            const int d4  = (idx & 15) << 2;
            *(float4*)&As[row][d4] = *(const float4*)(ab + (size_t)row * S_ + jc + d4);
            *(float4*)&Vs[row][d4] = *(const float4*)(vb + (size_t)(jc + row) * DV_ + d4);
        }
        __syncthreads();

        #pragma unroll 4
        for (int j4 = 0; j4 < 64; j4 += 4) {
            unsigned long long vv[4];
            #pragma unroll
            for (int kk = 0; kk < 4; kk++)
                vv[kk] = *(const unsigned long long*)&Vs[j4 + kk][l * 2];
            #pragma unroll
            for (int r = 0; r < 8; r++) {
                float4 a4 = *(const float4*)&As[w * 8 + r][j4];  // broadcast
                FMA2(acc[r], dup2(a4.x), vv[0]);
                FMA2(acc[r], dup2(a4.y), vv[1]);
                FMA2(acc[r], dup2(a4.z), vv[2]);
                FMA2(acc[r], dup2(a4.w), vv[3]);
            }
        }
    }

    float* ob = out + ((size_t)bh * S_ + i0 + w * 8) * DV_ + l * 2;
    #pragma unroll
    for (int r = 0; r < 8; r++) {
        float2 o = unpack2(acc[r]);
        *(float2*)(ob + (size_t)r * DV_) = o;
    }
}

// ---------------------------------------------------------------------------
extern "C" void kernel_launch(void* const* d_in, const int* in_sizes, int n_in,
                              void* d_out, int out_size)
{
    const float* q    = (const float*)d_in[0];
    const float* k    = (const float*)d_in[1];
    const float* v    = (const float*)d_in[2];
    const int*   mask = (const int*)d_in[3];
    const float* rpr  = (const float*)d_in[4];
    float* out  = (float*)d_out;
    float* attn = out + OUT_ATTN_OFF;

    cudaFuncSetAttribute(k1_qk, cudaFuncAttributeMaxDynamicSharedMemorySize, K1_SMEM);
    cudaFuncSetAttribute(k2_rpr_softmax, cudaFuncAttributeMaxDynamicSharedMemorySize,
                         K2_SMEM_TOTAL);

    {   // K1: attn1 logits into attn region (scratch, rewritten by K2)
        dim3 grid(S_ / 128, S_ / 128, B_ * H_);
        k1_qk<<<grid, 256, K1_SMEM>>>(q, k, attn);
    }
    {   // K2: + positional term, mask, softmax (in place)
        dim3 grid(S_, B_);
        k2_rpr_softmax<<<grid, 256, K2_SMEM_TOTAL>>>(q, rpr, mask, attn);
    }
    {   // K3: output = attn @ v
        dim3 grid(S_ / 64, B_ * H_);
        k3_av<<<grid, 256>>>(attn, v, out);
    }
}

// round 5
// speedup vs baseline: 1.0100x; 1.0100x over previous
#include <cuda_runtime.h>
#include <cstdint>

#define B_ 2
#define H_ 8
#define S_ 1024
#define DK_ 64
#define DV_ 64
static constexpr float INV_T = 0.125f;                   // 1/temperature
static constexpr int OUT_ATTN_OFF = B_ * H_ * S_ * DV_;  // 1048576

// ---- packed fp32 helpers (sm_103a f32x2 pipe) -------------------------------
#define FMA2(acc, a, b) asm("fma.rn.f32x2 %0, %1, %2, %0;" : "+l"(acc) : "l"(a), "l"(b))

__device__ __forceinline__ unsigned long long dup2(float x) {
    unsigned long long r;
    asm("mov.b64 %0, {%1, %1};" : "=l"(r) : "f"(x));
    return r;
}
__device__ __forceinline__ float2 unpack2(unsigned long long v) {
    float2 r;
    asm("mov.b64 {%0, %1}, %2;" : "=f"(r.x), "=f"(r.y) : "l"(v));
    return r;
}

// ---- cp.async helpers -------------------------------------------------------
__device__ __forceinline__ uint32_t s2u(const void* p) {
    return (uint32_t)__cvta_generic_to_shared(p);
}
__device__ __forceinline__ void cp8(uint32_t dst, const void* src) {
    asm volatile("cp.async.ca.shared.global [%0], [%1], 8;" :: "r"(dst), "l"(src));
}
__device__ __forceinline__ void cp16(uint32_t dst, const void* src) {
    asm volatile("cp.async.cg.shared.global [%0], [%1], 16;" :: "r"(dst), "l"(src));
}
#define CP_COMMIT() asm volatile("cp.async.commit_group;")
#define CP_WAIT1()  asm volatile("cp.async.wait_group 1;")
#define CP_WAIT0()  asm volatile("cp.async.wait_group 0;")

// ---------------------------------------------------------------------------
// K1: attn1[b,h,i,j] = (q/T)[b,h,i,:] . k[b,h,j,:]
// 128x128 CTA tile, 8x8 per-thread micro-tile, packed f32x2 accumulators.
// (unchanged from R3 — correct, crossbar/latency balanced)
// ---------------------------------------------------------------------------
static constexpr int K1_PITCH = 132;
static constexpr int K1_SMEM = 2 * 64 * K1_PITCH * 4;  // 67584 B

__global__ void __launch_bounds__(256) k1_qk(const float* __restrict__ q,
                                             const float* __restrict__ k,
                                             float* __restrict__ attn)
{
    extern __shared__ float sm1[];
    float* Qt = sm1;                   // [64][132]  Qt[d][i], pre-scaled by 1/T
    float* Kt = sm1 + 64 * K1_PITCH;   // [64][132]  Kt[d][j]

    const int bh = blockIdx.z;
    const int i0 = blockIdx.y * 128;
    const int j0 = blockIdx.x * 128;
    const float* qb = q + ((size_t)bh * S_ + i0) * DK_;
    const float* kb = k + ((size_t)bh * S_ + j0) * DK_;
    const int t = threadIdx.x;

    #pragma unroll
    for (int idx = t; idx < 2048; idx += 256) {
        const int row = idx & 127;
        const int d4  = ((idx >> 7) & 15) << 2;
        float4 a = *(const float4*)(qb + (size_t)row * DK_ + d4);
        Qt[(d4 + 0) * K1_PITCH + row] = a.x * INV_T;
        Qt[(d4 + 1) * K1_PITCH + row] = a.y * INV_T;
        Qt[(d4 + 2) * K1_PITCH + row] = a.z * INV_T;
        Qt[(d4 + 3) * K1_PITCH + row] = a.w * INV_T;
        float4 b = *(const float4*)(kb + (size_t)row * DK_ + d4);
        Kt[(d4 + 0) * K1_PITCH + row] = b.x;
        Kt[(d4 + 1) * K1_PITCH + row] = b.y;
        Kt[(d4 + 2) * K1_PITCH + row] = b.z;
        Kt[(d4 + 3) * K1_PITCH + row] = b.w;
    }
    __syncthreads();

    const int tx = t & 15, ty = t >> 4;
    const float* qp = Qt + ty * 8;
    const float* kp = Kt + tx * 8;

    unsigned long long acc[4][8] = {};

    #pragma unroll 4
    for (int d = 0; d < 64; d++) {
        const float* qd = qp + d * K1_PITCH;
        const float* kd = kp + d * K1_PITCH;
        ulonglong2 a01 = *(const ulonglong2*)qd;
        ulonglong2 a23 = *(const ulonglong2*)(qd + 4);
        float4 b0 = *(const float4*)kd;
        float4 b1 = *(const float4*)(kd + 4);
        unsigned long long av[4] = {a01.x, a01.y, a23.x, a23.y};
        unsigned long long bb[8] = {dup2(b0.x), dup2(b0.y), dup2(b0.z), dup2(b0.w),
                                    dup2(b1.x), dup2(b1.y), dup2(b1.z), dup2(b1.w)};
        #pragma unroll
        for (int p = 0; p < 4; p++)
            #pragma unroll
            for (int v = 0; v < 8; v++)
                FMA2(acc[p][v], av[p], bb[v]);
    }

    float* ab = attn + (((size_t)bh * S_ + i0 + ty * 8) * S_) + j0 + tx * 8;
    #pragma unroll
    for (int p = 0; p < 4; p++) {
        float r0[8], r1[8];
        #pragma unroll
        for (int v = 0; v < 8; v++) {
            float2 pv = unpack2(acc[p][v]);
            r0[v] = pv.x; r1[v] = pv.y;
        }
        float* row0 = ab + (size_t)(2 * p) * S_;
        float* row1 = ab + (size_t)(2 * p + 1) * S_;
        *(float4*)(row0)     = make_float4(r0[0], r0[1], r0[2], r0[3]);
        *(float4*)(row0 + 4) = make_float4(r0[4], r0[5], r0[6], r0[7]);
        *(float4*)(row1)     = make_float4(r1[0], r1[1], r1[2], r1[3]);
        *(float4*)(row1 + 4) = make_float4(r1[4], r1[5], r1[6], r1[7]);
    }
}

// ---------------------------------------------------------------------------
// K2: per (b,i): logits[h][j] = attn1[h][j] + qs[h,:] . rpr[b,i,j,:]
//     mask, softmax over j, write final probs. rpr streamed exactly once.
// Thread owns one j per chunk, all 8 heads (4 packed head-pair accumulators).
// NEW: double-buffered cp.async staging (8B ops into pitch-66 layout) so the
// 512 MB rpr DRAM stream overlaps compute. 1 CTA/SM (170 KB smem).
// ---------------------------------------------------------------------------
static constexpr int K2_CHUNK = 256;
static constexpr int K2_PITCH = 66;
static constexpr int K2_RS_FLOATS = K2_CHUNK * K2_PITCH;          // 16896
static constexpr int K2_SMEM_TOTAL = (512 + 8192 + 2 * K2_RS_FLOATS) * 4;  // 169984 B

__device__ __forceinline__ void k2_stage(uint32_t rs_u32, const float* __restrict__ src,
                                         int t)
{
    // 256 rows x 64 floats = 8192 8B-words; each thread issues 32 cp.async.8
    #pragma unroll
    for (int m = 0; m < 32; m++) {
        const int idx = m * 256 + t;
        const int jj  = idx >> 5;
        const int d2  = (idx & 31) << 1;
        cp8(rs_u32 + (uint32_t)(jj * K2_PITCH + d2) * 4u, src + idx * 2);
    }
    CP_COMMIT();
}

__global__ void __launch_bounds__(256, 1) k2_rpr_softmax(
    const float* __restrict__ q,
    const float* __restrict__ rpr,
    const int* __restrict__ mask,
    float* __restrict__ attn)
{
    extern __shared__ float sm2[];
    float* qs    = sm2;                       // [4][64][2]
    float* logit = sm2 + 512;                 // [8][1024]
    float* rs0   = sm2 + 512 + 8192;          // [256][66]
    float* rs1   = rs0 + K2_RS_FLOATS;        // [256][66]

    const int b = blockIdx.y;
    const int i = blockIdx.x;
    const int t = threadIdx.x;

    // qs[hp][d][c] = q[h=2hp+c][d] / T   (adjacent floats = head pair = f32x2)
    #pragma unroll
    for (int idx = t; idx < 512; idx += 256) {
        const int h = idx >> 6, d = idx & 63;
        qs[(((h >> 1) * 64) + d) * 2 + (h & 1)] =
            q[(((size_t)b * H_ + h) * S_ + i) * DK_ + d] * INV_T;
    }

    const float* rbase = rpr + ((size_t)b * S_ + i) * S_ * DK_;
    const int* mrow = mask + ((size_t)b * S_ + i) * S_;
    const uint32_t rs_u[2] = { s2u(rs0), s2u(rs1) };
    float* const rsp[2] = { rs0, rs1 };

    // prologue: stage chunk 0
    k2_stage(rs_u[0], rbase, t);

    #pragma unroll
    for (int c = 0; c < 4; c++) {
        const int jc = c * K2_CHUNK;
        const int j = jc + t;

        // prefetch mask + attn1 for this chunk (independent of rs)
        const int mk = mrow[j];
        float a1v[8];
        #pragma unroll
        for (int h = 0; h < 8; h++)
            a1v[h] = attn[(((size_t)b * H_ + h) * S_ + i) * S_ + j];

        // stage next chunk into the other buffer, then wait for current
        if (c < 3) {
            k2_stage(rs_u[(c + 1) & 1], rbase + (size_t)(jc + K2_CHUNK) * DK_, t);
            CP_WAIT1();
        } else {
            CP_WAIT0();
        }
        __syncthreads();

        unsigned long long acc[4] = {};
        const float* rr = rsp[c & 1] + t * K2_PITCH;
        #pragma unroll 8
        for (int d = 0; d < 64; d += 2) {
            float2 r2 = *(const float2*)(rr + d);
            unsigned long long rx = dup2(r2.x);
            unsigned long long ry = dup2(r2.y);
            #pragma unroll
            for (int hp = 0; hp < 4; hp++) {
                ulonglong2 qq = *(const ulonglong2*)(qs + hp * 128 + d * 2);
                FMA2(acc[hp], qq.x, rx);
                FMA2(acc[hp], qq.y, ry);
            }
        }

        #pragma unroll
        for (int hp = 0; hp < 4; hp++) {
            float2 av = unpack2(acc[hp]);
            logit[(2 * hp)     * 1024 + j] = mk ? (av.x + a1v[2 * hp])     : -1e9f;
            logit[(2 * hp + 1) * 1024 + j] = mk ? (av.y + a1v[2 * hp + 1]) : -1e9f;
        }
        __syncthreads();   // buffer fully consumed before it is restaged
    }

    // softmax: warp w handles head w
    const int w = t >> 5, lane = t & 31;
    const float* lrow = logit + w * 1024;
    float vals[32];
    float mx = -3.4e38f;
    #pragma unroll
    for (int m = 0; m < 32; m++) {
        vals[m] = lrow[lane + 32 * m];
        mx = fmaxf(mx, vals[m]);
    }
    #pragma unroll
    for (int o = 16; o > 0; o >>= 1) mx = fmaxf(mx, __shfl_xor_sync(0xffffffffu, mx, o));
    float sum = 0.f;
    #pragma unroll
    for (int m = 0; m < 32; m++) { vals[m] = __expf(vals[m] - mx); sum += vals[m]; }
    #pragma unroll
    for (int o = 16; o > 0; o >>= 1) sum += __shfl_xor_sync(0xffffffffu, sum, o);
    const float rinv = 1.0f / sum;

    float* arow = attn + (((size_t)b * H_ + w) * S_ + i) * S_;
    #pragma unroll
    for (int m = 0; m < 32; m++) arow[lane + 32 * m] = vals[m] * rinv;
}

// ---------------------------------------------------------------------------
// K3: output[b,h,i,:] = sum_j attn[b,h,i,j] * v[b,h,j,:]
// Broadcast-A, f32x2 accumulators (8 i-rows x n-pair per thread).
// NEW: double-buffered cp.async staging of (As, Vs) tiles.
// ---------------------------------------------------------------------------
static constexpr int K3_TILE_FLOATS = 64 * 64;                     // 4096
static constexpr int K3_SMEM = 4 * K3_TILE_FLOATS * 4;             // 65536 B

__device__ __forceinline__ void k3_stage(uint32_t as_u, uint32_t vs_u,
                                         const float* __restrict__ ab,
                                         const float* __restrict__ vb,
                                         int jc, int t)
{
    #pragma unroll
    for (int m = 0; m < 4; m++) {
        const int idx = m * 256 + t;
        const int row = idx >> 4;
        const int d4  = (idx & 15) << 2;
        cp16(as_u + (uint32_t)(row * 64 + d4) * 4u, ab + (size_t)row * S_ + jc + d4);
        cp16(vs_u + (uint32_t)(row * 64 + d4) * 4u, vb + (size_t)(jc + row) * DV_ + d4);
    }
    CP_COMMIT();
}

__global__ void __launch_bounds__(256) k3_av(const float* __restrict__ attn,
                                             const float* __restrict__ v,
                                             float* __restrict__ out)
{
    extern __shared__ float sm3[];
    float* Asb[2] = { sm3,                      sm3 + 2 * K3_TILE_FLOATS };
    float* Vsb[2] = { sm3 + K3_TILE_FLOATS,     sm3 + 3 * K3_TILE_FLOATS };

    const int bh = blockIdx.y;
    const int i0 = blockIdx.x * 64;
    const int t = threadIdx.x;
    const int w = t >> 5, l = t & 31;
    const float* ab = attn + ((size_t)bh * S_ + i0) * S_;
    const float* vb = v + (size_t)bh * S_ * DV_;
    const uint32_t as_u[2] = { s2u(Asb[0]), s2u(Asb[1]) };
    const uint32_t vs_u[2] = { s2u(Vsb[0]), s2u(Vsb[1]) };

    unsigned long long acc[8] = {};

    k3_stage(as_u[0], vs_u[0], ab, vb, 0, t);

    for (int c = 0; c < 16; c++) {
        if (c < 15) {
            k3_stage(as_u[(c + 1) & 1], vs_u[(c + 1) & 1], ab, vb, (c + 1) * 64, t);
            CP_WAIT1();
        } else {
            CP_WAIT0();
        }
        __syncthreads();

        const float* As = Asb[c & 1];
        const float* Vs = Vsb[c & 1];
        #pragma unroll 4
        for (int j4 = 0; j4 < 64; j4 += 4) {
            unsigned long long vv[4];
            #pragma unroll
            for (int kk = 0; kk < 4; kk++)
                vv[kk] = *(const unsigned long long*)&Vs[(j4 + kk) * 64 + l * 2];
            #pragma unroll
            for (int r = 0; r < 8; r++) {
                float4 a4 = *(const float4*)&As[(w * 8 + r) * 64 + j4];  // broadcast
                FMA2(acc[r], dup2(a4.x), vv[0]);
                FMA2(acc[r], dup2(a4.y), vv[1]);
                FMA2(acc[r], dup2(a4.z), vv[2]);
                FMA2(acc[r], dup2(a4.w), vv[3]);
            }
        }
        __syncthreads();   // tile consumed before it is restaged
    }

    float* ob = out + ((size_t)bh * S_ + i0 + w * 8) * DV_ + l * 2;
    #pragma unroll
    for (int r = 0; r < 8; r++) {
        float2 o = unpack2(acc[r]);
        *(float2*)(ob + (size_t)r * DV_) = o;
    }
}

// ---------------------------------------------------------------------------
extern "C" void kernel_launch(void* const* d_in, const int* in_sizes, int n_in,
                              void* d_out, int out_size)
{
    const float* q    = (const float*)d_in[0];
    const float* k    = (const float*)d_in[1];
    const float* v    = (const float*)d_in[2];
    const int*   mask = (const int*)d_in[3];
    const float* rpr  = (const float*)d_in[4];
    float* out  = (float*)d_out;
    float* attn = out + OUT_ATTN_OFF;

    cudaFuncSetAttribute(k1_qk, cudaFuncAttributeMaxDynamicSharedMemorySize, K1_SMEM);
    cudaFuncSetAttribute(k2_rpr_softmax, cudaFuncAttributeMaxDynamicSharedMemorySize,
                         K2_SMEM_TOTAL);
    cudaFuncSetAttribute(k3_av, cudaFuncAttributeMaxDynamicSharedMemorySize, K3_SMEM);

    {   // K1: attn1 logits into attn region (scratch, rewritten by K2)
        dim3 grid(S_ / 128, S_ / 128, B_ * H_);
        k1_qk<<<grid, 256, K1_SMEM>>>(q, k, attn);
    }
    {   // K2: + positional term, mask, softmax (in place)
        dim3 grid(S_, B_);
        k2_rpr_softmax<<<grid, 256, K2_SMEM_TOTAL>>>(q, rpr, mask, attn);
    }
    {   // K3: output = attn @ v
        dim3 grid(S_ / 64, B_ * H_);
        k3_av<<<grid, 256, K3_SMEM>>>(attn, v, out);
    }
}